// round 10
// baseline (speedup 1.0000x reference)
#include <cuda_runtime.h>
#include <math.h>

#define NB 64
#define NS 4096
#define NC 128
#define KTOP 64

#define PHY(p) ((p) ^ (((p) >> 4) & 15))
#define FULLM 0xFFFFFFFFu

// 128 MB scratch holding the (B, C, S) transposed data; FFT operates in-place on rows.
__device__ float g_tr[(size_t)NB * NC * NS];
// Twiddle table: g_tw[m] = exp(-2*pi*i*m/4096)
__device__ float2 g_tw[NS];

__device__ __forceinline__ int drev4(int p) {
    unsigned br = __brev((unsigned)p) >> 20;               // 12-bit bit reversal
    return (int)(((br & 0x555u) << 1) | ((br & 0xAAAu) >> 1));
}

__device__ __forceinline__ float2 cmul(float2 a, float2 b) {
    return make_float2(a.x * b.x - a.y * b.y, a.x * b.y + a.y * b.x);
}
__device__ __forceinline__ float2 cmulc(float2 a, float2 b) {   // a * conj(b)
    return make_float2(a.x * b.x + a.y * b.y, a.y * b.x - a.x * b.y);
}

// W16^k = exp(-2*pi*i*k/16); constant-index after unroll -> immediates
__device__ __forceinline__ float2 w16c(int idx) {
    const float cr[16] = { 1.f,  0.9238795325112867f,  0.7071067811865476f,  0.3826834323650898f,
                           0.f, -0.3826834323650898f, -0.7071067811865476f, -0.9238795325112867f,
                          -1.f, -0.9238795325112867f, -0.7071067811865476f, -0.3826834323650898f,
                           0.f,  0.3826834323650898f,  0.7071067811865476f,  0.9238795325112867f };
    const float ci[16] = { 0.f, -0.3826834323650898f, -0.7071067811865476f, -0.9238795325112867f,
                          -1.f, -0.9238795325112867f, -0.7071067811865476f, -0.3826834323650898f,
                           0.f,  0.3826834323650898f,  0.7071067811865476f,  0.9238795325112867f,
                           1.f,  0.9238795325112867f,  0.7071067811865476f,  0.3826834323650898f };
    return make_float2(cr[idx], ci[idx]);
}

// forward DFT4 (omega = -i)
__device__ __forceinline__ void bf4f(float2& a, float2& b, float2& c, float2& d) {
    float2 acp = make_float2(a.x + c.x, a.y + c.y);
    float2 acm = make_float2(a.x - c.x, a.y - c.y);
    float2 bdp = make_float2(b.x + d.x, b.y + d.y);
    float2 bdm = make_float2(b.x - d.x, b.y - d.y);
    a = make_float2(acp.x + bdp.x, acp.y + bdp.y);
    b = make_float2(acm.x + bdm.y, acm.y - bdm.x);   // acm - i*bdm
    c = make_float2(acp.x - bdp.x, acp.y - bdp.y);
    d = make_float2(acm.x - bdm.y, acm.y + bdm.x);   // acm + i*bdm
}
// inverse DFT4 (omega = +i)
__device__ __forceinline__ void bf4i(float2& a, float2& b, float2& c, float2& d) {
    float2 acp = make_float2(a.x + c.x, a.y + c.y);
    float2 acm = make_float2(a.x - c.x, a.y - c.y);
    float2 bdp = make_float2(b.x + d.x, b.y + d.y);
    float2 bdm = make_float2(b.x - d.x, b.y - d.y);
    a = make_float2(acp.x + bdp.x, acp.y + bdp.y);
    b = make_float2(acm.x - bdm.y, acm.y + bdm.x);   // acm + i*bdm
    c = make_float2(acp.x - bdp.x, acp.y - bdp.y);
    d = make_float2(acm.x + bdm.y, acm.y - bdm.x);
}

// 16-pt DIF in registers: input natural, output v[i] = Y_{rev2(i)}
__device__ __forceinline__ void sixteen_fwd(float2* v) {
    #pragma unroll
    for (int c = 0; c < 4; c++) {
        bf4f(v[c], v[c + 4], v[c + 8], v[c + 12]);
        if (c) {
            #pragma unroll
            for (int m = 1; m < 4; m++)
                v[c + 4 * m] = cmul(v[c + 4 * m], w16c(c * m));
        }
    }
    #pragma unroll
    for (int b = 0; b < 4; b++)
        bf4f(v[4 * b + 0], v[4 * b + 1], v[4 * b + 2], v[4 * b + 3]);
}

// 16-pt DIT inverse: input v[i] = Z_{rev2(i)} (ext twiddles pre-applied), output natural
__device__ __forceinline__ void sixteen_inv(float2* v) {
    #pragma unroll
    for (int b = 0; b < 4; b++)
        bf4i(v[4 * b + 0], v[4 * b + 1], v[4 * b + 2], v[4 * b + 3]);
    #pragma unroll
    for (int c = 1; c < 4; c++) {
        #pragma unroll
        for (int m = 1; m < 4; m++)
            v[c + 4 * m] = cmulc(v[c + 4 * m], w16c(c * m));
    }
    #pragma unroll
    for (int c = 0; c < 4; c++)
        bf4i(v[c], v[c + 4], v[c + 8], v[c + 12]);
}

template<int S, int G>
__device__ __forceinline__ void fwd_stage(float2* Xs, int tid) {
    int blk, t;
    if (S == 16)  { blk = tid >> 4;  t = tid & 15; }
    else          { blk = tid;       t = 0;        }
    int base = blk * 16 * S + t;
    float2 v[16];
    #pragma unroll
    for (int i = 0; i < 16; i++) v[i] = Xs[PHY(base + i * S)];
    sixteen_fwd(v);
    #pragma unroll
    for (int i = 0; i < 16; i++) {
        int r = ((i & 3) << 2) | (i >> 2);
        float2 o = v[i];
        if (S != 1 && r != 0) o = cmul(o, g_tw[t * G * r]);
        Xs[PHY(base + i * S)] = o;
    }
}

template<int S, int G>
__device__ __forceinline__ void inv_stage(float2* Xs, int tid) {
    int blk, t;
    if (S == 16)  { blk = tid >> 4;  t = tid & 15; }
    else          { blk = tid;       t = 0;        }
    int base = blk * 16 * S + t;
    float2 v[16];
    #pragma unroll
    for (int i = 0; i < 16; i++) {
        int r = ((i & 3) << 2) | (i >> 2);
        float2 x = Xs[PHY(base + i * S)];
        if (S != 1 && r != 0) x = cmulc(x, g_tw[t * G * r]);
        v[i] = x;
    }
    sixteen_inv(v);
    #pragma unroll
    for (int q = 0; q < 16; q++) Xs[PHY(base + q * S)] = v[q];
}

// Warp-parallel descending radix-select; EVERY warp runs this redundantly and
// keeps (pref, need) in registers (ballot+shfl broadcast; no smem state).
__device__ __forceinline__ void warp_select_reg(const unsigned* hist, unsigned& pref,
                                                unsigned& need, int shift) {
    const int lane = threadIdx.x & 31;
    unsigned c[8];
    unsigned s = 0;
    #pragma unroll
    for (int j = 0; j < 8; j++) { c[j] = hist[lane * 8 + j]; s += c[j]; }
    unsigned incl = s;
    #pragma unroll
    for (int d = 1; d < 32; d <<= 1) {
        unsigned t = __shfl_up_sync(FULLM, incl, d);
        if (lane >= d) incl += t;
    }
    unsigned total = __shfl_sync(FULLM, incl, 31);
    unsigned acc = total - incl;          // sum of all higher lanes' groups
    bool won = false;
    unsigned npref = pref, nneed = need;
    #pragma unroll
    for (int j = 7; j >= 0; j--) {
        unsigned cj = c[j];
        if (!won && acc < need && acc + cj >= need) {
            won = true;
            nneed = need - acc;
            npref = pref | ((unsigned)(lane * 8 + j) << shift);
        }
        acc += cj;
    }
    unsigned wm = __ballot_sync(FULLM, won);
    int src = __ffs(wm) - 1;
    pref = __shfl_sync(FULLM, npref, src);
    need = __shfl_sync(FULLM, nneed, src);
}

// ---------------- transpose (B,S,C) -> scratch (B,C,S); also fills twiddle table ----------------
__global__ __launch_bounds__(256) void k_t1(const float* __restrict__ in) {
    __shared__ float tile[32][33];
    const int b  = blockIdx.z;
    const int c0 = blockIdx.x * 32;
    const int s0 = blockIdx.y * 32;
    const int tid = threadIdx.x;
    const int q = tid & 7;       // quad index
    const int r = tid >> 3;      // row 0..31

    // 16 designated blocks compute the twiddle table (stream-ordered before k_fft)
    if (blockIdx.z == 0 && blockIdx.x == 0 && blockIdx.y < 16) {
        int m = blockIdx.y * 256 + tid;
        double ang = -2.0 * 3.14159265358979323846 * (double)m / (double)NS;
        g_tw[m] = make_float2((float)cos(ang), (float)sin(ang));
    }

    // load: float4 along C
    float4 lv = *(const float4*)&in[((size_t)b * NS + (s0 + r)) * NC + c0 + 4 * q];
    tile[r][4 * q + 0] = lv.x;
    tile[r][4 * q + 1] = lv.y;
    tile[r][4 * q + 2] = lv.z;
    tile[r][4 * q + 3] = lv.w;
    __syncthreads();

    // store: float4 along S
    float4 sv;
    sv.x = tile[4 * q + 0][r];
    sv.y = tile[4 * q + 1][r];
    sv.z = tile[4 * q + 2][r];
    sv.w = tile[4 * q + 3][r];
    *(float4*)&g_tr[((size_t)b * NC + (c0 + r)) * NS + s0 + 4 * q] = sv;
}

// ---------------- transpose scratch (B,C,S) -> out (B,S,C), float4 both sides ----------------
__global__ __launch_bounds__(256) void k_t3(float* __restrict__ out) {
    __shared__ float tile[32][33];
    const int b  = blockIdx.z;
    const int c0 = blockIdx.x * 32;
    const int s0 = blockIdx.y * 32;
    const int tid = threadIdx.x;
    const int q = tid & 7;
    const int r = tid >> 3;

    float4 lv = *(const float4*)&g_tr[((size_t)b * NC + (c0 + r)) * NS + s0 + 4 * q];
    tile[r][4 * q + 0] = lv.x;
    tile[r][4 * q + 1] = lv.y;
    tile[r][4 * q + 2] = lv.z;
    tile[r][4 * q + 3] = lv.w;
    __syncthreads();

    float4 sv;
    sv.x = tile[4 * q + 0][r];
    sv.y = tile[4 * q + 1][r];
    sv.z = tile[4 * q + 2][r];
    sv.w = tile[4 * q + 3][r];
    *(float4*)&out[((size_t)b * NS + (s0 + r)) * NC + c0 + 4 * q] = sv;
}

// ---------------- paired-channel: load+FFT -> split -> top-64 -> recombine -> iFFT+store ----------------
__global__ __launch_bounds__(256, 3) void k_fft() {
    __shared__ float2 X[NS];
    __shared__ unsigned hA[4][256], hB[4][256];   // one single-use buffer per select pass

    const int tid = threadIdx.x;
    const size_t row = (size_t)blockIdx.x * 2 * NS;
    const float* ap = g_tr + row;
    const float* bp = g_tr + row + NS;

    // ---- coalesced load + first fwd stage (S=256) in regs; zero all histograms ----
    {
        float2 v[16];
        #pragma unroll
        for (int i = 0; i < 16; i++)
            v[i] = make_float2(ap[tid + 256 * i], bp[tid + 256 * i]);
        #pragma unroll
        for (int h = 0; h < 4; h++) { hA[h][tid] = 0u; hB[h][tid] = 0u; }
        sixteen_fwd(v);
        #pragma unroll
        for (int i = 0; i < 16; i++) {
            int r = ((i & 3) << 2) | (i >> 2);
            float2 o = v[i];
            if (r) o = cmul(o, g_tw[tid * r]);
            X[PHY(tid + i * 256)] = o;
        }
    }
    __syncthreads();

    fwd_stage<16, 16>(X, tid);  __syncthreads();
    fwd_stage<1, 256>(X, tid);  __syncthreads();

    // ---- split Z -> A / conj(B), cache magnitudes in regs, fused pass-0 histogram ----
    unsigned uA[8], uB[8];
    unsigned uA2 = 0u, uB2 = 0u;     // bin-2048 mags (only tid 0 meaningful)
    const int kb = ((tid & 31) << 6) | ((tid >> 5) << 3);
    #pragma unroll
    for (int m = 0; m < 8; m++) {
        int k = kb + m;
        if (k) {
            int p  = PHY(drev4(k));
            int pn = PHY(drev4(NS - k));
            float2 z = X[p], zn = X[pn];
            float2 A  = make_float2(0.5f * (z.x + zn.x), 0.5f * (z.y - zn.y));
            float2 Bc = make_float2(0.5f * (z.y + zn.y), 0.5f * (zn.x - z.x));
            X[p] = A; X[pn] = Bc;
            uA[m] = __float_as_uint(A.x * A.x + A.y * A.y);
            uB[m] = __float_as_uint(Bc.x * Bc.x + Bc.y * Bc.y);
            atomicAdd(&hA[0][uA[m] >> 24], 1u);
            atomicAdd(&hB[0][uB[m] >> 24], 1u);
        } else {
            // tid==0, m==0: bins 0 and 2048 (self-conjugate, packed (A,B) as (re,im))
            float2 v0 = X[PHY(0)];
            float2 v2 = X[PHY(drev4(NS / 2))];
            uA[0] = __float_as_uint(v0.x * v0.x);
            uB[0] = __float_as_uint(v0.y * v0.y);
            uA2   = __float_as_uint(v2.x * v2.x);
            uB2   = __float_as_uint(v2.y * v2.y);
            atomicAdd(&hA[0][uA[0] >> 24], 1u);
            atomicAdd(&hB[0][uB[0] >> 24], 1u);
            atomicAdd(&hA[0][uA2 >> 24], 1u);
            atomicAdd(&hB[0][uB2 >> 24], 1u);
        }
    }
    __syncthreads();

    // ---- select: every warp redundantly computes the pivot in registers ----
    unsigned prefA = 0u, needA = KTOP, prefB = 0u, needB = KTOP;
    warp_select_reg(hA[0], prefA, needA, 24);
    warp_select_reg(hB[0], prefB, needB, 24);

    unsigned himask = 0xFF000000u;
    #pragma unroll
    for (int pass = 1; pass < 4; pass++) {
        const int shift = 24 - 8 * pass;
        #pragma unroll
        for (int m = 0; m < 8; m++) {
            unsigned ua = uA[m];
            if ((ua & himask) == prefA) atomicAdd(&hA[pass][(ua >> shift) & 255], 1u);
            unsigned ub = uB[m];
            if ((ub & himask) == prefB) atomicAdd(&hB[pass][(ub >> shift) & 255], 1u);
        }
        if (tid == 0) {
            if ((uA2 & himask) == prefA) atomicAdd(&hA[pass][(uA2 >> shift) & 255], 1u);
            if ((uB2 & himask) == prefB) atomicAdd(&hB[pass][(uB2 >> shift) & 255], 1u);
        }
        __syncthreads();
        warp_select_reg(hA[pass], prefA, needA, shift);
        warp_select_reg(hB[pass], prefB, needB, shift);
        himask = 0xFFFFFFFFu << shift;
    }
    const unsigned pivA = prefA;   // uint compare == float compare (non-negative)
    const unsigned pivB = prefB;

    // ---- mask (register mags vs pivot) + recombine Zf = Am + i*Bm (pair-private) ----
    #pragma unroll
    for (int m = 0; m < 8; m++) {
        int k = kb + m;
        if (k) {
            int p  = PHY(drev4(k));
            int pn = PHY(drev4(NS - k));
            float2 A = X[p], Bc = X[pn];
            if (uA[m] < pivA) A  = make_float2(0.f, 0.f);
            if (uB[m] < pivB) Bc = make_float2(0.f, 0.f);
            X[p]  = make_float2(A.x - Bc.y, A.y + Bc.x);
            X[pn] = make_float2(A.x + Bc.y, Bc.x - A.y);
        } else {
            float2 v0 = X[PHY(0)];
            v0.x = (uA[0] >= pivA) ? v0.x : 0.f;
            v0.y = (uB[0] >= pivB) ? v0.y : 0.f;
            X[PHY(0)] = v0;
            int p2 = PHY(drev4(NS / 2));
            float2 v2 = X[p2];
            v2.x = (uA2 >= pivA) ? v2.x : 0.f;
            v2.y = (uB2 >= pivB) ? v2.y : 0.f;
            X[p2] = v2;
        }
    }
    __syncthreads();

    inv_stage<1, 256>(X, tid);  __syncthreads();
    inv_stage<16, 16>(X, tid);  __syncthreads();

    // ---- last inverse stage (S=256) in regs + coalesced store ----
    {
        float2 u[16];
        #pragma unroll
        for (int i = 0; i < 16; i++) {
            int r = ((i & 3) << 2) | (i >> 2);
            float2 x = X[PHY(tid + i * 256)];
            if (r) x = cmulc(x, g_tw[tid * r]);
            u[i] = x;
        }
        sixteen_inv(u);
        const float invn = 1.0f / (float)NS;
        float* ao = g_tr + row;
        float* bo = g_tr + row + NS;
        #pragma unroll
        for (int q = 0; q < 16; q++) {
            ao[tid + q * 256] = u[q].x * invn;
            bo[tid + q * 256] = u[q].y * invn;
        }
    }
}

extern "C" void kernel_launch(void* const* d_in, const int* in_sizes, int n_in,
                              void* d_out, int out_size) {
    const float* in = (const float*)d_in[0];
    float* out = (float*)d_out;

    dim3 gt(NC / 32, NS / 32, NB);
    k_t1<<<gt, 256>>>(in);

    k_fft<<<NB * NC / 2, 256>>>();

    k_t3<<<gt, 256>>>(out);
}

// round 11
// speedup vs baseline: 1.4145x; 1.4145x over previous
#include <cuda_runtime.h>
#include <math.h>

#define NB 64
#define NS 4096
#define NC 128
#define KTOP 64

#define PHY(p) ((p) ^ (((p) >> 4) & 15))

// 128 MB scratch holding the (B, C, S) transposed data.
__device__ float g_tr[(size_t)NB * NC * NS];
// Twiddle table: g_tw[m] = exp(-2*pi*i*m/4096)
__device__ float2 g_tw[NS];

__device__ __forceinline__ int drev4(int p) {
    unsigned br = __brev((unsigned)p) >> 20;               // 12-bit bit reversal
    return (int)(((br & 0x555u) << 1) | ((br & 0xAAAu) >> 1));
}

__device__ __forceinline__ float2 cmul(float2 a, float2 b) {
    return make_float2(a.x * b.x - a.y * b.y, a.x * b.y + a.y * b.x);
}
__device__ __forceinline__ float2 cmulc(float2 a, float2 b) {   // a * conj(b)
    return make_float2(a.x * b.x + a.y * b.y, a.y * b.x - a.x * b.y);
}

// W16^k = exp(-2*pi*i*k/16); constant-index after unroll -> immediates
__device__ __forceinline__ float2 w16c(int idx) {
    const float cr[16] = { 1.f,  0.9238795325112867f,  0.7071067811865476f,  0.3826834323650898f,
                           0.f, -0.3826834323650898f, -0.7071067811865476f, -0.9238795325112867f,
                          -1.f, -0.9238795325112867f, -0.7071067811865476f, -0.3826834323650898f,
                           0.f,  0.3826834323650898f,  0.7071067811865476f,  0.9238795325112867f };
    const float ci[16] = { 0.f, -0.3826834323650898f, -0.7071067811865476f, -0.9238795325112867f,
                          -1.f, -0.9238795325112867f, -0.7071067811865476f, -0.3826834323650898f,
                           0.f,  0.3826834323650898f,  0.7071067811865476f,  0.9238795325112867f,
                           1.f,  0.9238795325112867f,  0.7071067811865476f,  0.3826834323650898f };
    return make_float2(cr[idx], ci[idx]);
}

// forward DFT4 (omega = -i)
__device__ __forceinline__ void bf4f(float2& a, float2& b, float2& c, float2& d) {
    float2 acp = make_float2(a.x + c.x, a.y + c.y);
    float2 acm = make_float2(a.x - c.x, a.y - c.y);
    float2 bdp = make_float2(b.x + d.x, b.y + d.y);
    float2 bdm = make_float2(b.x - d.x, b.y - d.y);
    a = make_float2(acp.x + bdp.x, acp.y + bdp.y);
    b = make_float2(acm.x + bdm.y, acm.y - bdm.x);   // acm - i*bdm
    c = make_float2(acp.x - bdp.x, acp.y - bdp.y);
    d = make_float2(acm.x - bdm.y, acm.y + bdm.x);   // acm + i*bdm
}
// inverse DFT4 (omega = +i)
__device__ __forceinline__ void bf4i(float2& a, float2& b, float2& c, float2& d) {
    float2 acp = make_float2(a.x + c.x, a.y + c.y);
    float2 acm = make_float2(a.x - c.x, a.y - c.y);
    float2 bdp = make_float2(b.x + d.x, b.y + d.y);
    float2 bdm = make_float2(b.x - d.x, b.y - d.y);
    a = make_float2(acp.x + bdp.x, acp.y + bdp.y);
    b = make_float2(acm.x - bdm.y, acm.y + bdm.x);   // acm + i*bdm
    c = make_float2(acp.x - bdp.x, acp.y - bdp.y);
    d = make_float2(acm.x + bdm.y, acm.y - bdm.x);
}

// 16-pt DIF in registers: input natural, output v[i] = Y_{rev2(i)}
__device__ __forceinline__ void sixteen_fwd(float2* v) {
    #pragma unroll
    for (int c = 0; c < 4; c++) {
        bf4f(v[c], v[c + 4], v[c + 8], v[c + 12]);
        if (c) {
            #pragma unroll
            for (int m = 1; m < 4; m++)
                v[c + 4 * m] = cmul(v[c + 4 * m], w16c(c * m));
        }
    }
    #pragma unroll
    for (int b = 0; b < 4; b++)
        bf4f(v[4 * b + 0], v[4 * b + 1], v[4 * b + 2], v[4 * b + 3]);
}

// 16-pt DIT inverse: input v[i] = Z_{rev2(i)} (ext twiddles pre-applied), output natural
__device__ __forceinline__ void sixteen_inv(float2* v) {
    #pragma unroll
    for (int b = 0; b < 4; b++)
        bf4i(v[4 * b + 0], v[4 * b + 1], v[4 * b + 2], v[4 * b + 3]);
    #pragma unroll
    for (int c = 1; c < 4; c++) {
        #pragma unroll
        for (int m = 1; m < 4; m++)
            v[c + 4 * m] = cmulc(v[c + 4 * m], w16c(c * m));
    }
    #pragma unroll
    for (int c = 0; c < 4; c++)
        bf4i(v[c], v[c + 4], v[c + 8], v[c + 12]);
}

template<int S, int G>
__device__ __forceinline__ void fwd_stage(float2* Xs, int tid) {
    int blk, t;
    if (S == 16)  { blk = tid >> 4;  t = tid & 15; }
    else          { blk = tid;       t = 0;        }
    int base = blk * 16 * S + t;
    float2 v[16];
    #pragma unroll
    for (int i = 0; i < 16; i++) v[i] = Xs[PHY(base + i * S)];
    sixteen_fwd(v);
    #pragma unroll
    for (int i = 0; i < 16; i++) {
        int r = ((i & 3) << 2) | (i >> 2);
        float2 o = v[i];
        if (S != 1 && r != 0) o = cmul(o, g_tw[t * G * r]);
        Xs[PHY(base + i * S)] = o;
    }
}

template<int S, int G>
__device__ __forceinline__ void inv_stage(float2* Xs, int tid) {
    int blk, t;
    if (S == 16)  { blk = tid >> 4;  t = tid & 15; }
    else          { blk = tid;       t = 0;        }
    int base = blk * 16 * S + t;
    float2 v[16];
    #pragma unroll
    for (int i = 0; i < 16; i++) {
        int r = ((i & 3) << 2) | (i >> 2);
        float2 x = Xs[PHY(base + i * S)];
        if (S != 1 && r != 0) x = cmulc(x, g_tw[t * G * r]);
        v[i] = x;
    }
    sixteen_inv(v);
    #pragma unroll
    for (int q = 0; q < 16; q++) Xs[PHY(base + q * S)] = v[q];
}

// Warp-parallel descending radix-select step over a 256-bucket histogram.
__device__ __forceinline__ void warp_select(const unsigned* hist, unsigned* sPref,
                                            unsigned* sNeed, int shift, unsigned prefOld) {
    const int lane = threadIdx.x & 31;
    unsigned c[8];
    unsigned s = 0;
    #pragma unroll
    for (int j = 0; j < 8; j++) { c[j] = hist[lane * 8 + j]; s += c[j]; }
    unsigned incl = s;
    #pragma unroll
    for (int d = 1; d < 32; d <<= 1) {
        unsigned t = __shfl_up_sync(0xFFFFFFFFu, incl, d);
        if (lane >= d) incl += t;
    }
    unsigned total = __shfl_sync(0xFFFFFFFFu, incl, 31);
    unsigned above = total - incl;
    const unsigned need = *sNeed;
    unsigned acc = above;
    #pragma unroll
    for (int j = 7; j >= 0; j--) {
        unsigned cj = c[j];
        if (acc < need && acc + cj >= need) {
            *sNeed = need - acc;
            *sPref = prefOld | ((unsigned)(lane * 8 + j) << shift);
        }
        acc += cj;
    }
}

// ---------------- twiddle init ----------------
__global__ void k_tw() {
    int m = blockIdx.x * blockDim.x + threadIdx.x;
    if (m < NS) {
        double ang = -2.0 * 3.14159265358979323846 * (double)m / (double)NS;
        g_tw[m] = make_float2((float)cos(ang), (float)sin(ang));
    }
}

// ---------------- transpose (B,S,C) -> scratch (B,C,S), float4 both sides ----------------
__global__ __launch_bounds__(256) void k_t1(const float* __restrict__ in) {
    __shared__ float tile[32][33];
    const int b  = blockIdx.z;
    const int c0 = blockIdx.x * 32;
    const int s0 = blockIdx.y * 32;
    const int tid = threadIdx.x;
    const int q = tid & 7;       // quad index
    const int r = tid >> 3;      // row 0..31

    // load: float4 along C
    float4 lv = *(const float4*)&in[((size_t)b * NS + (s0 + r)) * NC + c0 + 4 * q];
    tile[r][4 * q + 0] = lv.x;
    tile[r][4 * q + 1] = lv.y;
    tile[r][4 * q + 2] = lv.z;
    tile[r][4 * q + 3] = lv.w;
    __syncthreads();

    // store: float4 along S
    float4 sv;
    sv.x = tile[4 * q + 0][r];
    sv.y = tile[4 * q + 1][r];
    sv.z = tile[4 * q + 2][r];
    sv.w = tile[4 * q + 3][r];
    *(float4*)&g_tr[((size_t)b * NC + (c0 + r)) * NS + s0 + 4 * q] = sv;
}

// ---------------- paired-channel: load+FFT -> split -> top-64 -> recombine -> iFFT -> direct (B,S,C) store ----------------
__global__ __launch_bounds__(256, 3) void k_fft(float2* __restrict__ out2) {
    __shared__ float2 X[NS];
    __shared__ unsigned hA[2][256], hB[2][256];
    __shared__ unsigned sPrefA, sPrefB, sNeedA, sNeedB;

    const int tid = threadIdx.x;
    const size_t row = (size_t)blockIdx.x * 2 * NS;
    const int b  = blockIdx.x >> 6;       // batch
    const int c2 = blockIdx.x & 63;       // channel-pair index
    const float* ap = g_tr + row;
    const float* bp = g_tr + row + NS;

    // ---- coalesced load + first fwd stage (S=256) in regs ----
    {
        float2 v[16];
        #pragma unroll
        for (int i = 0; i < 16; i++)
            v[i] = make_float2(ap[tid + 256 * i], bp[tid + 256 * i]);
        if (tid == 0) { sPrefA = 0; sPrefB = 0; sNeedA = KTOP; sNeedB = KTOP; }
        hA[0][tid] = 0u; hB[0][tid] = 0u;
        sixteen_fwd(v);
        #pragma unroll
        for (int i = 0; i < 16; i++) {
            int r = ((i & 3) << 2) | (i >> 2);
            float2 o = v[i];
            if (r) o = cmul(o, g_tw[tid * r]);
            X[PHY(tid + i * 256)] = o;
        }
    }
    __syncthreads();

    fwd_stage<16, 16>(X, tid);  __syncwarp();   // stage16 -> stage1 is 16-thread-local
    fwd_stage<1, 256>(X, tid);  __syncthreads();

    // ---- split Z -> A / conj(B), cache magnitudes in regs, fused pass-0 histogram ----
    unsigned uA[8], uB[8];
    unsigned uA2 = 0u, uB2 = 0u;     // bin-2048 mags (only tid 0 meaningful)
    const int kb = ((tid & 31) << 6) | ((tid >> 5) << 3);
    hA[1][tid] = 0u; hB[1][tid] = 0u;
    #pragma unroll
    for (int m = 0; m < 8; m++) {
        int k = kb + m;
        if (k) {
            int p  = PHY(drev4(k));
            int pn = PHY(drev4(NS - k));
            float2 z = X[p], zn = X[pn];
            float2 A  = make_float2(0.5f * (z.x + zn.x), 0.5f * (z.y - zn.y));
            float2 Bc = make_float2(0.5f * (z.y + zn.y), 0.5f * (zn.x - z.x));
            X[p] = A; X[pn] = Bc;
            uA[m] = __float_as_uint(A.x * A.x + A.y * A.y);
            uB[m] = __float_as_uint(Bc.x * Bc.x + Bc.y * Bc.y);
            atomicAdd(&hA[0][uA[m] >> 24], 1u);
            atomicAdd(&hB[0][uB[m] >> 24], 1u);
        } else {
            // tid==0, m==0: bins 0 and 2048 (self-conjugate, packed (A,B) as (re,im))
            float2 v0 = X[PHY(0)];
            float2 v2 = X[PHY(drev4(NS / 2))];
            uA[0] = __float_as_uint(v0.x * v0.x);
            uB[0] = __float_as_uint(v0.y * v0.y);
            uA2   = __float_as_uint(v2.x * v2.x);
            uB2   = __float_as_uint(v2.y * v2.y);
            atomicAdd(&hA[0][uA[0] >> 24], 1u);
            atomicAdd(&hB[0][uB[0] >> 24], 1u);
            atomicAdd(&hA[0][uA2 >> 24], 1u);
            atomicAdd(&hB[0][uB2 >> 24], 1u);
        }
    }
    __syncthreads();
    if (tid < 32)            warp_select(hA[0], &sPrefA, &sNeedA, 24, 0u);
    else if (tid < 64)       warp_select(hB[0], &sPrefB, &sNeedB, 24, 0u);
    __syncthreads();

    // ---- remaining 3 radix-select passes, fully register-sourced ----
    unsigned himask = 0xFF000000u;
    #pragma unroll
    for (int pass = 1; pass < 4; pass++) {
        const int shift = 24 - 8 * pass;
        const int buf   = pass & 1;
        const unsigned pA = sPrefA, pB = sPrefB;
        hA[buf ^ 1][tid] = 0u; hB[buf ^ 1][tid] = 0u;
        #pragma unroll
        for (int m = 0; m < 8; m++) {
            unsigned ua = uA[m];
            if ((ua & himask) == pA) atomicAdd(&hA[buf][(ua >> shift) & 255], 1u);
            unsigned ub = uB[m];
            if ((ub & himask) == pB) atomicAdd(&hB[buf][(ub >> shift) & 255], 1u);
        }
        if (tid == 0) {
            if ((uA2 & himask) == pA) atomicAdd(&hA[buf][(uA2 >> shift) & 255], 1u);
            if ((uB2 & himask) == pB) atomicAdd(&hB[buf][(uB2 >> shift) & 255], 1u);
        }
        __syncthreads();
        if (tid < 32)        warp_select(hA[buf], &sPrefA, &sNeedA, shift, pA);
        else if (tid < 64)   warp_select(hB[buf], &sPrefB, &sNeedB, shift, pB);
        himask = 0xFFFFFFFFu << shift;
        __syncthreads();
    }
    const unsigned pivA = sPrefA;   // uint compare == float compare (non-negative)
    const unsigned pivB = sPrefB;

    // ---- mask (register mags vs pivot) + recombine Zf = Am + i*Bm ----
    #pragma unroll
    for (int m = 0; m < 8; m++) {
        int k = kb + m;
        if (k) {
            int p  = PHY(drev4(k));
            int pn = PHY(drev4(NS - k));
            float2 A = X[p], Bc = X[pn];
            if (uA[m] < pivA) A  = make_float2(0.f, 0.f);
            if (uB[m] < pivB) Bc = make_float2(0.f, 0.f);
            X[p]  = make_float2(A.x - Bc.y, A.y + Bc.x);
            X[pn] = make_float2(A.x + Bc.y, Bc.x - A.y);
        } else {
            float2 v0 = X[PHY(0)];
            v0.x = (uA[0] >= pivA) ? v0.x : 0.f;
            v0.y = (uB[0] >= pivB) ? v0.y : 0.f;
            X[PHY(0)] = v0;
            int p2 = PHY(drev4(NS / 2));
            float2 v2 = X[p2];
            v2.x = (uA2 >= pivA) ? v2.x : 0.f;
            v2.y = (uB2 >= pivB) ? v2.y : 0.f;
            X[p2] = v2;
        }
    }
    __syncthreads();

    inv_stage<1, 256>(X, tid);  __syncwarp();   // inv1 -> inv16 is 16-thread-local
    inv_stage<16, 16>(X, tid);  __syncthreads();

    // ---- last inverse stage (S=256) in regs + DIRECT (B,S,C) store ----
    {
        float2 u[16];
        #pragma unroll
        for (int i = 0; i < 16; i++) {
            int r = ((i & 3) << 2) | (i >> 2);
            float2 x = X[PHY(tid + i * 256)];
            if (r) x = cmulc(x, g_tw[tid * r]);
            u[i] = x;
        }
        sixteen_inv(u);
        const float invn = 1.0f / (float)NS;
        // out element (b, s, c): float2 index (b*NS + s)*(NC/2) + c2, s = tid + 256q
        float2* o = out2 + ((size_t)b * NS + tid) * (NC / 2) + c2;
        #pragma unroll
        for (int q = 0; q < 16; q++) {
            o[(size_t)q * 256 * (NC / 2)] =
                make_float2(u[q].x * invn, u[q].y * invn);
        }
    }
}

extern "C" void kernel_launch(void* const* d_in, const int* in_sizes, int n_in,
                              void* d_out, int out_size) {
    const float* in = (const float*)d_in[0];
    float2* out2 = (float2*)d_out;

    k_tw<<<(NS + 255) / 256, 256>>>();

    dim3 gt(NC / 32, NS / 32, NB);
    k_t1<<<gt, 256>>>(in);

    k_fft<<<NB * NC / 2, 256>>>(out2);
}

// round 13
// speedup vs baseline: 1.5488x; 1.0950x over previous
#include <cuda_runtime.h>
#include <math.h>

#define NB 64
#define NS 4096
#define NC 128
#define KTOP 64

#define PHY(p) ((p) ^ (((p) >> 4) & 15))

typedef unsigned long long u64c;   // packed complex: lo32 = re, hi32 = im

// 128 MB scratch holding the (B, C, S) transposed data.
__device__ float g_tr[(size_t)NB * NC * NS];
// Packed twiddle table: g_tw4[m] = (c, s, -s, c), angle = -2*pi*m/4096
__device__ float4 g_tw4[NS];

__device__ __forceinline__ int drev4(int p) {
    unsigned br = __brev((unsigned)p) >> 20;               // 12-bit bit reversal
    return (int)(((br & 0x555u) << 1) | ((br & 0xAAAu) >> 1));
}

// ---- packed complex primitives (f32x2) ----
__device__ __forceinline__ u64c cadd2(u64c a, u64c b) {
    u64c r; asm("add.rn.f32x2 %0,%1,%2;" : "=l"(r) : "l"(a), "l"(b)); return r;
}
__device__ __forceinline__ u64c csub2(u64c a, u64c b) {
    u64c r; asm("sub.rn.f32x2 %0,%1,%2;" : "=l"(r) : "l"(a), "l"(b)); return r;
}
__device__ __forceinline__ u64c cscale2(u64c a, u64c s) {
    u64c r; asm("mul.rn.f32x2 %0,%1,%2;" : "=l"(r) : "l"(a), "l"(s)); return r;
}
__device__ __forceinline__ u64c cmuli(u64c z) {   // i*z = (-y, x)
    unsigned lo = (unsigned)z, hi = (unsigned)(z >> 32);
    return ((u64c)lo << 32) | (u64c)(hi ^ 0x80000000u);
}
__device__ __forceinline__ u64c cnegi(u64c z) {   // -i*z = (y, -x)
    unsigned lo = (unsigned)z, hi = (unsigned)(z >> 32);
    return ((u64c)(lo ^ 0x80000000u) << 32) | (u64c)hi;
}
// a * w, where wA = (w.re, w.im), wB = (-w.im, w.re)
__device__ __forceinline__ u64c cmul2(u64c a, u64c wA, u64c wB) {
    unsigned al = (unsigned)a, ah = (unsigned)(a >> 32);
    u64c axx = ((u64c)al << 32) | (u64c)al;
    u64c ayy = ((u64c)ah << 32) | (u64c)ah;
    u64c t, r;
    asm("mul.rn.f32x2 %0,%1,%2;" : "=l"(t) : "l"(ayy), "l"(wB));
    asm("fma.rn.f32x2 %0,%1,%2,%3;" : "=l"(r) : "l"(axx), "l"(wA), "l"(t));
    return r;
}
// a * conj(w) from the same (wA, wB) pair
__device__ __forceinline__ u64c cmulc2(u64c a, u64c wA, u64c wB) {
    return cmul2(a, wA ^ 0x8000000000000000ULL, wB ^ 0x0000000080000000ULL);
}

// packed constants: c1=cos(pi/8)=0x3F6C835E, s1=sin(pi/8)=0x3EC3EF15, r=0x3F3504F3
#define W1A 0xBEC3EF153F6C835EULL   // ( c1,-s1)
#define W1B 0x3F6C835E3EC3EF15ULL   // ( s1, c1)
#define W3A 0xBF6C835E3EC3EF15ULL   // ( s1,-c1)
#define W3B 0x3EC3EF153F6C835EULL   // ( c1, s1)
#define C1A 0x3EC3EF153F6C835EULL   // ( c1, s1)
#define C1B 0x3F6C835EBEC3EF15ULL   // (-s1, c1)
#define C3A 0x3F6C835E3EC3EF15ULL   // ( s1, c1)
#define C3B 0x3EC3EF15BF6C835EULL   // (-c1, s1)
#define RRC 0x3F3504F33F3504F3ULL   // ( r, r)
#define NRC 0xBF3504F3BF3504F3ULL   // (-r,-r)
#define NEGBOTH 0x8000000080000000ULL
#define INVN 0x3980000039800000ULL  // (1/4096, 1/4096)

// forward DFT4 (omega = -i), packed
__device__ __forceinline__ void bf4f2(u64c& a, u64c& b, u64c& c, u64c& d) {
    u64c acp = cadd2(a, c), acm = csub2(a, c);
    u64c bdp = cadd2(b, d), bdm = csub2(b, d);
    u64c sn = cnegi(bdm);                  // -i*bdm
    a = cadd2(acp, bdp);  c = csub2(acp, bdp);
    b = cadd2(acm, sn);   d = csub2(acm, sn);
}
// inverse DFT4 (omega = +i), packed
__device__ __forceinline__ void bf4i2(u64c& a, u64c& b, u64c& c, u64c& d) {
    u64c acp = cadd2(a, c), acm = csub2(a, c);
    u64c bdp = cadd2(b, d), bdm = csub2(b, d);
    u64c sp = cmuli(bdm);                  // +i*bdm
    a = cadd2(acp, bdp);  c = csub2(acp, bdp);
    b = cadd2(acm, sp);   d = csub2(acm, sp);
}

// fwd mul by W16^2 = r*(1,-1):  r*(x+y, y-x)
__device__ __forceinline__ u64c mw2f(u64c a) { return cscale2(cadd2(a, cnegi(a)), RRC); }
// fwd mul by W16^6 = -r*(1,1):  (r(y-x), -r(x+y))
__device__ __forceinline__ u64c mw6f(u64c a) { return cscale2(cadd2(a, cmuli(a)), NRC); }
// inv mul by conj(W16^2) = r*(1,1):  (r(x-y), r(x+y))
__device__ __forceinline__ u64c mw2i(u64c a) { return cscale2(cadd2(a, cmuli(a)), RRC); }
// inv mul by conj(W16^6) = (-r, r):  (-r(x+y), r(x-y))
__device__ __forceinline__ u64c mw6i(u64c a) { return cscale2(cadd2(a, cnegi(a)), NRC); }

// 16-pt DIF packed: input natural, output v[i] = Y_{rev2(i)}
__device__ __forceinline__ void sixteen_fwd2(u64c* v) {
    bf4f2(v[0], v[4], v[8], v[12]);
    bf4f2(v[1], v[5], v[9], v[13]);
    v[5]  = cmul2(v[5], W1A, W1B);          // W^1
    v[9]  = mw2f(v[9]);                     // W^2
    v[13] = cmul2(v[13], W3A, W3B);         // W^3
    bf4f2(v[2], v[6], v[10], v[14]);
    v[6]  = mw2f(v[6]);                     // W^2
    v[10] = cnegi(v[10]);                   // W^4 = -i
    v[14] = mw6f(v[14]);                    // W^6
    bf4f2(v[3], v[7], v[11], v[15]);
    v[7]  = cmul2(v[7], W3A, W3B);          // W^3
    v[11] = mw6f(v[11]);                    // W^6
    v[15] = cmul2(v[15], W1A, W1B) ^ NEGBOTH;   // W^9 = -W^1
    #pragma unroll
    for (int b = 0; b < 4; b++)
        bf4f2(v[4 * b + 0], v[4 * b + 1], v[4 * b + 2], v[4 * b + 3]);
}

// 16-pt DIT inverse packed: input v[i] = Z_{rev2(i)}, output natural
__device__ __forceinline__ void sixteen_inv2(u64c* v) {
    #pragma unroll
    for (int b = 0; b < 4; b++)
        bf4i2(v[4 * b + 0], v[4 * b + 1], v[4 * b + 2], v[4 * b + 3]);
    v[5]  = cmul2(v[5], C1A, C1B);          // conj W^1
    v[9]  = mw2i(v[9]);                     // conj W^2
    v[13] = cmul2(v[13], C3A, C3B);         // conj W^3
    v[6]  = mw2i(v[6]);
    v[10] = cmuli(v[10]);                   // conj W^4 = +i
    v[14] = mw6i(v[14]);
    v[7]  = cmul2(v[7], C3A, C3B);
    v[11] = mw6i(v[11]);
    v[15] = cmul2(v[15], C1A, C1B) ^ NEGBOTH;   // conj W^9
    bf4i2(v[0], v[4], v[8], v[12]);
    bf4i2(v[1], v[5], v[9], v[13]);
    bf4i2(v[2], v[6], v[10], v[14]);
    bf4i2(v[3], v[7], v[11], v[15]);
}

template<int S, int G>
__device__ __forceinline__ void fwd_stage2(u64c* Xs, const ulonglong2* tw, int tid) {
    int blk, t;
    if (S == 16)  { blk = tid >> 4;  t = tid & 15; }
    else          { blk = tid;       t = 0;        }
    int base = blk * 16 * S + t;
    u64c v[16];
    #pragma unroll
    for (int i = 0; i < 16; i++) v[i] = Xs[PHY(base + i * S)];
    sixteen_fwd2(v);
    #pragma unroll
    for (int i = 0; i < 16; i++) {
        int r = ((i & 3) << 2) | (i >> 2);
        u64c o = v[i];
        if (S != 1 && r != 0) {
            ulonglong2 w = tw[t * G * r];
            o = cmul2(o, w.x, w.y);
        }
        Xs[PHY(base + i * S)] = o;
    }
}

template<int S, int G>
__device__ __forceinline__ void inv_stage2(u64c* Xs, const ulonglong2* tw, int tid) {
    int blk, t;
    if (S == 16)  { blk = tid >> 4;  t = tid & 15; }
    else          { blk = tid;       t = 0;        }
    int base = blk * 16 * S + t;
    u64c v[16];
    #pragma unroll
    for (int i = 0; i < 16; i++) {
        int r = ((i & 3) << 2) | (i >> 2);
        u64c x = Xs[PHY(base + i * S)];
        if (S != 1 && r != 0) {
            ulonglong2 w = tw[t * G * r];
            x = cmulc2(x, w.x, w.y);
        }
        v[i] = x;
    }
    sixteen_inv2(v);
    #pragma unroll
    for (int q = 0; q < 16; q++) Xs[PHY(base + q * S)] = v[q];
}

// Warp-parallel descending radix-select step over a 256-bucket histogram.
__device__ __forceinline__ void warp_select(const unsigned* hist, unsigned* sPref,
                                            unsigned* sNeed, int shift, unsigned prefOld) {
    const int lane = threadIdx.x & 31;
    unsigned c[8];
    unsigned s = 0;
    #pragma unroll
    for (int j = 0; j < 8; j++) { c[j] = hist[lane * 8 + j]; s += c[j]; }
    unsigned incl = s;
    #pragma unroll
    for (int d = 1; d < 32; d <<= 1) {
        unsigned t = __shfl_up_sync(0xFFFFFFFFu, incl, d);
        if (lane >= d) incl += t;
    }
    unsigned total = __shfl_sync(0xFFFFFFFFu, incl, 31);
    unsigned above = total - incl;
    const unsigned need = *sNeed;
    unsigned acc = above;
    #pragma unroll
    for (int j = 7; j >= 0; j--) {
        unsigned cj = c[j];
        if (acc < need && acc + cj >= need) {
            *sNeed = need - acc;
            *sPref = prefOld | ((unsigned)(lane * 8 + j) << shift);
        }
        acc += cj;
    }
}

// ---------------- twiddle init (packed table) ----------------
__global__ void k_tw() {
    int m = blockIdx.x * blockDim.x + threadIdx.x;
    if (m < NS) {
        double ang = -2.0 * 3.14159265358979323846 * (double)m / (double)NS;
        float c = (float)cos(ang), s = (float)sin(ang);
        g_tw4[m] = make_float4(c, s, -s, c);
    }
}

// ---------------- transpose (B,S,C) -> scratch (B,C,S), float4 both sides ----------------
__global__ __launch_bounds__(256) void k_t1(const float* __restrict__ in) {
    __shared__ float tile[32][33];
    const int b  = blockIdx.z;
    const int c0 = blockIdx.x * 32;
    const int s0 = blockIdx.y * 32;
    const int tid = threadIdx.x;
    const int q = tid & 7;
    const int r = tid >> 3;

    float4 lv = *(const float4*)&in[((size_t)b * NS + (s0 + r)) * NC + c0 + 4 * q];
    tile[r][4 * q + 0] = lv.x;
    tile[r][4 * q + 1] = lv.y;
    tile[r][4 * q + 2] = lv.z;
    tile[r][4 * q + 3] = lv.w;
    __syncthreads();

    float4 sv;
    sv.x = tile[4 * q + 0][r];
    sv.y = tile[4 * q + 1][r];
    sv.z = tile[4 * q + 2][r];
    sv.w = tile[4 * q + 3][r];
    *(float4*)&g_tr[((size_t)b * NC + (c0 + r)) * NS + s0 + 4 * q] = sv;
}

// ---------------- transpose scratch (B,C,S) -> out (B,S,C), float4 both sides ----------------
__global__ __launch_bounds__(256) void k_t3(float* __restrict__ out) {
    __shared__ float tile[32][33];
    const int b  = blockIdx.z;
    const int c0 = blockIdx.x * 32;
    const int s0 = blockIdx.y * 32;
    const int tid = threadIdx.x;
    const int q = tid & 7;
    const int r = tid >> 3;

    float4 lv = *(const float4*)&g_tr[((size_t)b * NC + (c0 + r)) * NS + s0 + 4 * q];
    tile[r][4 * q + 0] = lv.x;
    tile[r][4 * q + 1] = lv.y;
    tile[r][4 * q + 2] = lv.z;
    tile[r][4 * q + 3] = lv.w;
    __syncthreads();

    float4 sv;
    sv.x = tile[4 * q + 0][r];
    sv.y = tile[4 * q + 1][r];
    sv.z = tile[4 * q + 2][r];
    sv.w = tile[4 * q + 3][r];
    *(float4*)&out[((size_t)b * NS + (s0 + r)) * NC + c0 + 4 * q] = sv;
}

// ---------------- paired-channel: load+FFT -> split -> top-64 -> recombine -> iFFT+store ----------------
__global__ __launch_bounds__(256, 3) void k_fft() {
    __shared__ u64c X[NS];
    __shared__ unsigned hA[2][256], hB[2][256];
    __shared__ unsigned sPrefA, sPrefB, sNeedA, sNeedB;

    const int tid = threadIdx.x;
    const size_t row = (size_t)blockIdx.x * 2 * NS;
    const float* ap = g_tr + row;
    const float* bp = g_tr + row + NS;
    const ulonglong2* tw = (const ulonglong2*)g_tw4;
    float2* Xf = (float2*)X;

    // ---- coalesced load + first fwd stage (S=256) in regs ----
    {
        u64c v[16];
        #pragma unroll
        for (int i = 0; i < 16; i++) {
            unsigned ai = __float_as_uint(ap[tid + 256 * i]);
            unsigned bi = __float_as_uint(bp[tid + 256 * i]);
            v[i] = ((u64c)bi << 32) | (u64c)ai;    // z = a + i*b
        }
        if (tid == 0) { sPrefA = 0; sPrefB = 0; sNeedA = KTOP; sNeedB = KTOP; }
        hA[0][tid] = 0u; hB[0][tid] = 0u;
        sixteen_fwd2(v);
        #pragma unroll
        for (int i = 0; i < 16; i++) {
            int r = ((i & 3) << 2) | (i >> 2);
            u64c o = v[i];
            if (r) {
                ulonglong2 w = tw[tid * r];
                o = cmul2(o, w.x, w.y);
            }
            X[PHY(tid + i * 256)] = o;
        }
    }
    __syncthreads();

    fwd_stage2<16, 16>(X, tw, tid);  __syncwarp();   // stage16 -> stage1 is 16-thread-local
    fwd_stage2<1, 256>(X, tw, tid);  __syncthreads();

    // ---- split Z -> A / conj(B), cache magnitudes in regs, fused pass-0 histogram ----
    unsigned uA[8], uB[8];
    unsigned uA2 = 0u, uB2 = 0u;     // bin-2048 mags (only tid 0 meaningful)
    const int kb = ((tid & 31) << 6) | ((tid >> 5) << 3);
    hA[1][tid] = 0u; hB[1][tid] = 0u;
    #pragma unroll
    for (int m = 0; m < 8; m++) {
        int k = kb + m;
        if (k) {
            int p  = PHY(drev4(k));
            int pn = PHY(drev4(NS - k));
            float2 z = Xf[p], zn = Xf[pn];
            float2 A  = make_float2(0.5f * (z.x + zn.x), 0.5f * (z.y - zn.y));
            float2 Bc = make_float2(0.5f * (z.y + zn.y), 0.5f * (zn.x - z.x));
            Xf[p] = A; Xf[pn] = Bc;
            uA[m] = __float_as_uint(A.x * A.x + A.y * A.y);
            uB[m] = __float_as_uint(Bc.x * Bc.x + Bc.y * Bc.y);
            atomicAdd(&hA[0][uA[m] >> 24], 1u);
            atomicAdd(&hB[0][uB[m] >> 24], 1u);
        } else {
            float2 v0 = Xf[PHY(0)];
            float2 v2 = Xf[PHY(drev4(NS / 2))];
            uA[0] = __float_as_uint(v0.x * v0.x);
            uB[0] = __float_as_uint(v0.y * v0.y);
            uA2   = __float_as_uint(v2.x * v2.x);
            uB2   = __float_as_uint(v2.y * v2.y);
            atomicAdd(&hA[0][uA[0] >> 24], 1u);
            atomicAdd(&hB[0][uB[0] >> 24], 1u);
            atomicAdd(&hA[0][uA2 >> 24], 1u);
            atomicAdd(&hB[0][uB2 >> 24], 1u);
        }
    }
    __syncthreads();
    if (tid < 32)            warp_select(hA[0], &sPrefA, &sNeedA, 24, 0u);
    else if (tid < 64)       warp_select(hB[0], &sPrefB, &sNeedB, 24, 0u);
    __syncthreads();

    // ---- remaining 3 radix-select passes, fully register-sourced ----
    unsigned himask = 0xFF000000u;
    #pragma unroll
    for (int pass = 1; pass < 4; pass++) {
        const int shift = 24 - 8 * pass;
        const int buf   = pass & 1;
        const unsigned pA = sPrefA, pB = sPrefB;
        hA[buf ^ 1][tid] = 0u; hB[buf ^ 1][tid] = 0u;
        #pragma unroll
        for (int m = 0; m < 8; m++) {
            unsigned ua = uA[m];
            if ((ua & himask) == pA) atomicAdd(&hA[buf][(ua >> shift) & 255], 1u);
            unsigned ub = uB[m];
            if ((ub & himask) == pB) atomicAdd(&hB[buf][(ub >> shift) & 255], 1u);
        }
        if (tid == 0) {
            if ((uA2 & himask) == pA) atomicAdd(&hA[buf][(uA2 >> shift) & 255], 1u);
            if ((uB2 & himask) == pB) atomicAdd(&hB[buf][(uB2 >> shift) & 255], 1u);
        }
        __syncthreads();
        if (tid < 32)        warp_select(hA[buf], &sPrefA, &sNeedA, shift, pA);
        else if (tid < 64)   warp_select(hB[buf], &sPrefB, &sNeedB, shift, pB);
        himask = 0xFFFFFFFFu << shift;
        __syncthreads();
    }
    const unsigned pivA = sPrefA;   // uint compare == float compare (non-negative)
    const unsigned pivB = sPrefB;

    // ---- mask (register mags vs pivot) + recombine Zf = Am + i*Bm ----
    #pragma unroll
    for (int m = 0; m < 8; m++) {
        int k = kb + m;
        if (k) {
            int p  = PHY(drev4(k));
            int pn = PHY(drev4(NS - k));
            float2 A = Xf[p], Bc = Xf[pn];
            if (uA[m] < pivA) A  = make_float2(0.f, 0.f);
            if (uB[m] < pivB) Bc = make_float2(0.f, 0.f);
            Xf[p]  = make_float2(A.x - Bc.y, A.y + Bc.x);
            Xf[pn] = make_float2(A.x + Bc.y, Bc.x - A.y);
        } else {
            float2 v0 = Xf[PHY(0)];
            v0.x = (uA[0] >= pivA) ? v0.x : 0.f;
            v0.y = (uB[0] >= pivB) ? v0.y : 0.f;
            Xf[PHY(0)] = v0;
            int p2 = PHY(drev4(NS / 2));
            float2 v2 = Xf[p2];
            v2.x = (uA2 >= pivA) ? v2.x : 0.f;
            v2.y = (uB2 >= pivB) ? v2.y : 0.f;
            Xf[p2] = v2;
        }
    }
    __syncthreads();

    inv_stage2<1, 256>(X, tw, tid);  __syncwarp();   // inv1 -> inv16 is 16-thread-local
    inv_stage2<16, 16>(X, tw, tid);  __syncthreads();

    // ---- last inverse stage (S=256) in regs + coalesced store ----
    {
        u64c u[16];
        #pragma unroll
        for (int i = 0; i < 16; i++) {
            int r = ((i & 3) << 2) | (i >> 2);
            u64c x = X[PHY(tid + i * 256)];
            if (r) {
                ulonglong2 w = tw[tid * r];
                x = cmulc2(x, w.x, w.y);
            }
            u[i] = x;
        }
        sixteen_inv2(u);
        float* ao = g_tr + row;
        float* bo = g_tr + row + NS;
        #pragma unroll
        for (int q = 0; q < 16; q++) {
            u64c s = cscale2(u[q], INVN);
            ao[tid + q * 256] = __uint_as_float((unsigned)s);
            bo[tid + q * 256] = __uint_as_float((unsigned)(s >> 32));
        }
    }
}

extern "C" void kernel_launch(void* const* d_in, const int* in_sizes, int n_in,
                              void* d_out, int out_size) {
    const float* in = (const float*)d_in[0];
    float* out = (float*)d_out;

    k_tw<<<(NS + 255) / 256, 256>>>();

    dim3 gt(NC / 32, NS / 32, NB);
    k_t1<<<gt, 256>>>(in);

    k_fft<<<NB * NC / 2, 256>>>();

    k_t3<<<gt, 256>>>(out);
}